// round 1
// baseline (speedup 1.0000x reference)
#include <cuda_runtime.h>

// Problem constants
#define Bsz 16
#define Sl  2048
#define Hd  768
#define NT        (Bsz*(Sl-1))   // 32752 tokens for GEMMs
#define NTOK_FULL (Bsz*Sl)       // 32768

// Scratch (device globals — no allocation allowed in kernel_launch)
__device__ float g_sequ[(size_t)NTOK_FULL*Hd]; // seqs + E_u[u]
__device__ float g_ph  [(size_t)NT*Hd];        // relu(pairs @ W_hid^T)
__device__ float g_dc  [(size_t)NT*128];       // relu(cat(de,ce) @ W_cd^T)
__device__ float g_m   [(size_t)NT*Hd];        // relu(cat(ph,dc) @ W_cdh^T)

__device__ __forceinline__ float4 ld4(const float* p){
    return *reinterpret_cast<const float4*>(p);
}

// ---------------------------------------------------------------------------
// Kernel 1: seqs_u = seqs + E_u[u]
// One block per token, 192 threads x float4 = 768 floats.
// ---------------------------------------------------------------------------
__global__ void add_ue_k(const float* __restrict__ seqs,
                         const int*   __restrict__ u,
                         const float* __restrict__ Eu){
    int t = blockIdx.x;
    int uid = __ldg(&u[t]);
    const float4* s4 = reinterpret_cast<const float4*>(seqs + (size_t)t*Hd);
    const float4* e4 = reinterpret_cast<const float4*>(Eu   + (size_t)uid*Hd);
    float4*       d4 = reinterpret_cast<float4*>(g_sequ + (size_t)t*Hd);
    int i = threadIdx.x;
    float4 a = s4[i], b = e4[i];
    d4[i] = make_float4(a.x+b.x, a.y+b.y, a.z+b.z, a.w+b.w);
}

// ---------------------------------------------------------------------------
// Generic tiled fp32 GEMM-with-ReLU: C[t, n] = relu( sum_k A[t,k] * W[n,k] )
// BLOCK 128x128, K-tile 16, 256 threads, 8x8 per-thread microtile.
// MODE 0: A = [E_d[d[t]] | E_c[c[t]]],   K=256,  OUT=128, C=g_dc
// MODE 1: A = seqs_u pairs (contiguous), K=1536, OUT=768, C=g_ph
// MODE 2: A = [g_ph[t] | g_dc[t]],       K=896,  OUT=768, C=g_m
// Segment boundaries (128, 768) are multiples of 16 -> a 16-wide K tile never
// straddles a segment, so each float4 load lives in exactly one source.
// ---------------------------------------------------------------------------
template<int MODE, int K, int OUT>
__global__ __launch_bounds__(256, 2)
void gemm_relu_k(const float* __restrict__ A0, const float* __restrict__ A1,
                 const int*   __restrict__ I0, const int*   __restrict__ I1,
                 const float* __restrict__ W){
    __shared__ float As[16][132];   // pad 132: 2-way store conflicts, clean reads
    __shared__ float Bs[16][132];

    const int tid = threadIdx.x;
    const int m0  = blockIdx.x * 128;
    const int n0  = blockIdx.y * 128;
    const int ty  = tid >> 4;       // 0..15
    const int tx  = tid & 15;       // 0..15

    float* Cout;
    if (MODE == 0)      Cout = g_dc;
    else if (MODE == 1) Cout = g_ph;
    else                Cout = g_m;

    float acc[8][8];
    #pragma unroll
    for (int i = 0; i < 8; i++)
        #pragma unroll
        for (int j = 0; j < 8; j++) acc[i][j] = 0.f;

    for (int k0 = 0; k0 < K; k0 += 16){
        #pragma unroll
        for (int it = 0; it < 2; it++){
            int idx = tid + it*256;        // 0..511
            int r   = idx >> 2;            // 0..127 row within tile
            int kq  = (idx & 3) << 2;      // 0,4,8,12
            int k   = k0 + kq;

            // ---- A tile ----
            int t = m0 + r;
            float4 va = make_float4(0.f, 0.f, 0.f, 0.f);
            if (t < NT){
                if (MODE == 0){
                    if (k < 128) va = ld4(A0 + (size_t)__ldg(&I0[t])*128 + k);
                    else         va = ld4(A1 + (size_t)__ldg(&I1[t])*128 + (k-128));
                } else if (MODE == 1){
                    int row = t + t/2047;  // (b*2048 + s) given t = b*2047 + s
                    va = ld4(g_sequ + (size_t)row*Hd + k);
                } else {
                    if (k < 768) va = ld4(g_ph + (size_t)t*768 + k);
                    else         va = ld4(g_dc + (size_t)t*128 + (k-768));
                }
            }
            As[kq+0][r]=va.x; As[kq+1][r]=va.y; As[kq+2][r]=va.z; As[kq+3][r]=va.w;

            // ---- B tile: W[n, k], n = n0 + r ----
            float4 vb = ld4(W + (size_t)(n0 + r)*K + k);
            Bs[kq+0][r]=vb.x; Bs[kq+1][r]=vb.y; Bs[kq+2][r]=vb.z; Bs[kq+3][r]=vb.w;
        }
        __syncthreads();

        #pragma unroll
        for (int kk = 0; kk < 16; kk++){
            float a[8], b[8];
            *reinterpret_cast<float4*>(a)   = *reinterpret_cast<const float4*>(&As[kk][ty*4]);
            *reinterpret_cast<float4*>(a+4) = *reinterpret_cast<const float4*>(&As[kk][64+ty*4]);
            *reinterpret_cast<float4*>(b)   = *reinterpret_cast<const float4*>(&Bs[kk][tx*4]);
            *reinterpret_cast<float4*>(b+4) = *reinterpret_cast<const float4*>(&Bs[kk][64+tx*4]);
            #pragma unroll
            for (int i = 0; i < 8; i++)
                #pragma unroll
                for (int j = 0; j < 8; j++)
                    acc[i][j] = fmaf(a[i], b[j], acc[i][j]);
        }
        __syncthreads();
    }

    // Store with ReLU. Rows: ty*4..+3 and 64+ty*4..+3; cols: tx*4 and 64+tx*4.
    #pragma unroll
    for (int i = 0; i < 8; i++){
        int mrow = (i < 4) ? (ty*4 + i) : (64 + ty*4 + (i-4));
        int t = m0 + mrow;
        if (t < NT){
            float4 o0, o1;
            o0.x = fmaxf(acc[i][0], 0.f); o0.y = fmaxf(acc[i][1], 0.f);
            o0.z = fmaxf(acc[i][2], 0.f); o0.w = fmaxf(acc[i][3], 0.f);
            o1.x = fmaxf(acc[i][4], 0.f); o1.y = fmaxf(acc[i][5], 0.f);
            o1.z = fmaxf(acc[i][6], 0.f); o1.w = fmaxf(acc[i][7], 0.f);
            *reinterpret_cast<float4*>(Cout + (size_t)t*OUT + n0 + tx*4)      = o0;
            *reinterpret_cast<float4*>(Cout + (size_t)t*OUT + n0 + 64 + tx*4) = o1;
        }
    }
}

// ---------------------------------------------------------------------------
// Kernel 5: out[b,s] = seqs_u[b,s] + (s<S-1 ? m[b,s] : 0) + (s>=2 ? m[b,s-1] : 0)
// ---------------------------------------------------------------------------
__global__ void final_k(float* __restrict__ out){
    int t = blockIdx.x;          // 0..B*S-1
    int s = t & (Sl - 1);        // S = 2048 (power of two)
    int b = t >> 11;
    int i = threadIdx.x;

    float4 v = reinterpret_cast<const float4*>(g_sequ + (size_t)t*Hd)[i];
    size_t mb = (size_t)b * (Sl - 1);
    if (s < Sl - 1){
        float4 mv = reinterpret_cast<const float4*>(g_m + (mb + s)*Hd)[i];
        v.x += mv.x; v.y += mv.y; v.z += mv.z; v.w += mv.w;
    }
    if (s >= 2){
        float4 mv = reinterpret_cast<const float4*>(g_m + (mb + s - 1)*Hd)[i];
        v.x += mv.x; v.y += mv.y; v.z += mv.z; v.w += mv.w;
    }
    reinterpret_cast<float4*>(out + (size_t)t*Hd)[i] = v;
}

// ---------------------------------------------------------------------------
extern "C" void kernel_launch(void* const* d_in, const int* in_sizes, int n_in,
                              void* d_out, int out_size){
    const float* seqs  = (const float*)d_in[0];
    const int*   d_idx = (const int*)  d_in[1];
    const int*   c_idx = (const int*)  d_in[2];
    const int*   u_idx = (const int*)  d_in[3];
    const float* E_d   = (const float*)d_in[4];
    const float* E_c   = (const float*)d_in[5];
    const float* E_u   = (const float*)d_in[6];
    const float* W_cd  = (const float*)d_in[7];
    const float* W_hid = (const float*)d_in[8];
    const float* W_cdh = (const float*)d_in[9];
    float* out = (float*)d_out;

    const int MBLK = (NT + 127) / 128;   // 256

    // seqs_u = seqs + E_u[u]
    add_ue_k<<<NTOK_FULL, 192>>>(seqs, u_idx, E_u);

    // d_c = relu(cat(E_d[d], E_c[c]) @ W_cd^T)   [NT,128]
    gemm_relu_k<0, 256, 128><<<dim3(MBLK, 1), 256>>>(E_d, E_c, d_idx, c_idx, W_cd);

    // ph = relu(pairs @ W_hid^T)                 [NT,768]
    gemm_relu_k<1, 1536, 768><<<dim3(MBLK, 6), 256>>>(nullptr, nullptr, nullptr, nullptr, W_hid);

    // m = relu(cat(ph, d_c) @ W_cdh^T)           [NT,768]
    gemm_relu_k<2, 896, 768><<<dim3(MBLK, 6), 256>>>(nullptr, nullptr, nullptr, nullptr, W_cdh);

    // out = seqs_u + shifted m adds
    final_k<<<NTOK_FULL, 192>>>(out);
}

// round 2
// speedup vs baseline: 2.4349x; 2.4349x over previous
#include <cuda_runtime.h>
#include <cstdint>

// Problem constants
#define Bsz 16
#define Sl  2048
#define Hd  768
#define NT        (Bsz*(Sl-1))   // 32752 tokens for GEMMs
#define NTOK_FULL (Bsz*Sl)       // 32768

// Scratch (device globals — no allocation allowed in kernel_launch)
__device__ float g_sequ[(size_t)NTOK_FULL*Hd]; // seqs + E_u[u]
__device__ float g_ph  [(size_t)NT*Hd];        // relu(pairs @ W_hid^T)
__device__ float g_dc  [(size_t)NT*128];       // relu(cat(de,ce) @ W_cd^T)
__device__ float g_m   [(size_t)NT*Hd];        // relu(cat(ph,dc) @ W_cdh^T)

__device__ __forceinline__ float4 ld4(const float* p){
    return *reinterpret_cast<const float4*>(p);
}

__device__ __forceinline__ uint32_t f2tf32(float f){
    uint32_t o;
    asm("cvt.rna.tf32.f32 %0, %1;" : "=r"(o) : "f"(f));
    return o;
}

// ---------------------------------------------------------------------------
// Kernel 1: seqs_u = seqs + E_u[u]
// ---------------------------------------------------------------------------
__global__ void add_ue_k(const float* __restrict__ seqs,
                         const int*   __restrict__ u,
                         const float* __restrict__ Eu){
    int t = blockIdx.x;
    int uid = __ldg(&u[t]);
    const float4* s4 = reinterpret_cast<const float4*>(seqs + (size_t)t*Hd);
    const float4* e4 = reinterpret_cast<const float4*>(Eu   + (size_t)uid*Hd);
    float4*       d4 = reinterpret_cast<float4*>(g_sequ + (size_t)t*Hd);
    int i = threadIdx.x;
    float4 a = s4[i], b = e4[i];
    d4[i] = make_float4(a.x+b.x, a.y+b.y, a.z+b.z, a.w+b.w);
}

// ---------------------------------------------------------------------------
// TF32 tensor-core GEMM with fused gather inputs and ReLU epilogue.
//   C[t, n] = relu( sum_k A[t,k] * W[n,k] )
// Block tile 128(M) x 128(N), KTILE=32, 256 threads = 8 warps (4x2),
// warp tile 32x64 -> 2x8 fragments of m16n8k8.
// blockIdx.x = N-block (fast-varying -> concurrent CTAs share A tile in L2)
// blockIdx.y = M-block
// MODE 0: A = [E_d[d[t]] | E_c[c[t]]],   K=256,  OUT=128, C=g_dc
// MODE 1: A = seqs_u pairs (contiguous), K=1536, OUT=768, C=g_ph
// MODE 2: A = [g_ph[t] | g_dc[t]],       K=896,  OUT=768, C=g_m
// ---------------------------------------------------------------------------
#define KTILE 32
#define SSTR  36   // smem row stride: (4*g + c) mod 32 unique -> conflict-free

template<int MODE, int K, int OUT>
__global__ __launch_bounds__(256, 2)
void gemm_tc_k(const float* __restrict__ A0, const float* __restrict__ A1,
               const int*   __restrict__ I0, const int*   __restrict__ I1,
               const float* __restrict__ W){
    __shared__ uint32_t As[128*SSTR];
    __shared__ uint32_t Bs[128*SSTR];

    const int tid  = threadIdx.x;
    const int lane = tid & 31;
    const int warp = tid >> 5;
    const int m0   = blockIdx.y * 128;
    const int n0   = blockIdx.x * 128;
    const int wm   = (warp >> 1) * 32;
    const int wn   = (warp &  1) * 64;
    const int g    = lane >> 2;   // group
    const int c    = lane &  3;   // thread-in-group

    float* Cout;
    if (MODE == 0)      Cout = g_dc;
    else if (MODE == 1) Cout = g_ph;
    else                Cout = g_m;

    float acc[2][8][4];
    #pragma unroll
    for (int mi = 0; mi < 2; mi++)
        #pragma unroll
        for (int ni = 0; ni < 8; ni++)
            #pragma unroll
            for (int q = 0; q < 4; q++) acc[mi][ni][q] = 0.f;

    for (int k0 = 0; k0 < K; k0 += KTILE){
        // ---- load tiles: 128 rows x 32 k each; 1024 float4 over 256 threads
        #pragma unroll
        for (int it = 0; it < 4; it++){
            int idx = tid + it*256;         // 0..1023
            int r   = idx >> 3;             // 0..127
            int kq  = (idx & 7) << 2;       // 0,4,..,28
            int k   = k0 + kq;

            // A tile
            int t = m0 + r;
            float4 va = make_float4(0.f,0.f,0.f,0.f);
            if (t < NT){
                if (MODE == 0){
                    if (k < 128) va = ld4(A0 + (size_t)__ldg(&I0[t])*128 + k);
                    else         va = ld4(A1 + (size_t)__ldg(&I1[t])*128 + (k-128));
                } else if (MODE == 1){
                    int row = t + t/2047;   // (b*2048 + s) from t = b*2047 + s
                    va = ld4(g_sequ + (size_t)row*Hd + k);
                } else {
                    if (k < 768) va = ld4(g_ph + (size_t)t*768 + k);
                    else         va = ld4(g_dc + (size_t)t*128 + (k-768));
                }
            }
            uint4 ua = make_uint4(f2tf32(va.x), f2tf32(va.y), f2tf32(va.z), f2tf32(va.w));
            *reinterpret_cast<uint4*>(&As[r*SSTR + kq]) = ua;

            // B tile: W[n0+r, k]
            float4 vb = ld4(W + (size_t)(n0 + r)*K + k);
            uint4 ub = make_uint4(f2tf32(vb.x), f2tf32(vb.y), f2tf32(vb.z), f2tf32(vb.w));
            *reinterpret_cast<uint4*>(&Bs[r*SSTR + kq]) = ub;
        }
        __syncthreads();

        // ---- 4 inner k-steps of 8
        #pragma unroll
        for (int ks = 0; ks < KTILE; ks += 8){
            uint32_t afr[2][4], bfr[8][2];
            #pragma unroll
            for (int mi = 0; mi < 2; mi++){
                int r = wm + mi*16 + g;
                afr[mi][0] = As[ r     *SSTR + ks + c    ];
                afr[mi][1] = As[(r + 8)*SSTR + ks + c    ];
                afr[mi][2] = As[ r     *SSTR + ks + c + 4];
                afr[mi][3] = As[(r + 8)*SSTR + ks + c + 4];
            }
            #pragma unroll
            for (int ni = 0; ni < 8; ni++){
                int n = wn + ni*8 + g;
                bfr[ni][0] = Bs[n*SSTR + ks + c    ];
                bfr[ni][1] = Bs[n*SSTR + ks + c + 4];
            }
            #pragma unroll
            for (int mi = 0; mi < 2; mi++)
                #pragma unroll
                for (int ni = 0; ni < 8; ni++){
                    asm volatile(
                        "mma.sync.aligned.m16n8k8.row.col.f32.tf32.tf32.f32 "
                        "{%0,%1,%2,%3}, {%4,%5,%6,%7}, {%8,%9}, {%0,%1,%2,%3};\n"
                        : "+f"(acc[mi][ni][0]), "+f"(acc[mi][ni][1]),
                          "+f"(acc[mi][ni][2]), "+f"(acc[mi][ni][3])
                        : "r"(afr[mi][0]), "r"(afr[mi][1]),
                          "r"(afr[mi][2]), "r"(afr[mi][3]),
                          "r"(bfr[ni][0]), "r"(bfr[ni][1]));
                }
        }
        __syncthreads();
    }

    // ---- epilogue: ReLU + store (float2, cols 2c,2c+1 contiguous)
    #pragma unroll
    for (int mi = 0; mi < 2; mi++){
        int rbase = m0 + wm + mi*16 + g;
        #pragma unroll
        for (int half = 0; half < 2; half++){
            int t = rbase + half*8;
            if (t < NT){
                #pragma unroll
                for (int ni = 0; ni < 8; ni++){
                    float2 v;
                    v.x = fmaxf(acc[mi][ni][half*2 + 0], 0.f);
                    v.y = fmaxf(acc[mi][ni][half*2 + 1], 0.f);
                    *reinterpret_cast<float2*>(
                        Cout + (size_t)t*OUT + n0 + wn + ni*8 + 2*c) = v;
                }
            }
        }
    }
}

// ---------------------------------------------------------------------------
// Final: out[b,s] = seqs_u[b,s] + (s<S-1 ? m[b,s] : 0) + (s>=2 ? m[b,s-1] : 0)
// ---------------------------------------------------------------------------
__global__ void final_k(float* __restrict__ out){
    int t = blockIdx.x;          // 0..B*S-1
    int s = t & (Sl - 1);
    int b = t >> 11;
    int i = threadIdx.x;

    float4 v = reinterpret_cast<const float4*>(g_sequ + (size_t)t*Hd)[i];
    size_t mb = (size_t)b * (Sl - 1);
    if (s < Sl - 1){
        float4 mv = reinterpret_cast<const float4*>(g_m + (mb + s)*Hd)[i];
        v.x += mv.x; v.y += mv.y; v.z += mv.z; v.w += mv.w;
    }
    if (s >= 2){
        float4 mv = reinterpret_cast<const float4*>(g_m + (mb + s - 1)*Hd)[i];
        v.x += mv.x; v.y += mv.y; v.z += mv.z; v.w += mv.w;
    }
    reinterpret_cast<float4*>(out + (size_t)t*Hd)[i] = v;
}

// ---------------------------------------------------------------------------
extern "C" void kernel_launch(void* const* d_in, const int* in_sizes, int n_in,
                              void* d_out, int out_size){
    const float* seqs  = (const float*)d_in[0];
    const int*   d_idx = (const int*)  d_in[1];
    const int*   c_idx = (const int*)  d_in[2];
    const int*   u_idx = (const int*)  d_in[3];
    const float* E_d   = (const float*)d_in[4];
    const float* E_c   = (const float*)d_in[5];
    const float* E_u   = (const float*)d_in[6];
    const float* W_cd  = (const float*)d_in[7];
    const float* W_hid = (const float*)d_in[8];
    const float* W_cdh = (const float*)d_in[9];
    float* out = (float*)d_out;

    const int MBLK = (NT + 127) / 128;   // 256

    // seqs_u = seqs + E_u[u]
    add_ue_k<<<NTOK_FULL, 192>>>(seqs, u_idx, E_u);

    // d_c = relu(cat(E_d[d], E_c[c]) @ W_cd^T)   [NT,128]
    gemm_tc_k<0, 256, 128><<<dim3(1, MBLK), 256>>>(E_d, E_c, d_idx, c_idx, W_cd);

    // ph = relu(pairs @ W_hid^T)                 [NT,768]
    gemm_tc_k<1, 1536, 768><<<dim3(6, MBLK), 256>>>(nullptr, nullptr, nullptr, nullptr, W_hid);

    // m = relu(cat(ph, d_c) @ W_cdh^T)           [NT,768]
    gemm_tc_k<2, 896, 768><<<dim3(6, MBLK), 256>>>(nullptr, nullptr, nullptr, nullptr, W_cdh);

    // out = seqs_u + shifted m adds
    final_k<<<NTOK_FULL, 192>>>(out);
}

// round 3
// speedup vs baseline: 3.0970x; 1.2719x over previous
#include <cuda_runtime.h>
#include <cstdint>

// Problem constants
#define Bsz 16
#define Sl  2048
#define Hd  768
#define NT        (Bsz*(Sl-1))   // 32752 tokens for GEMMs
#define NTOK_FULL (Bsz*Sl)       // 32768

// Scratch (device globals — no allocation allowed in kernel_launch)
__device__ float g_sequ  [(size_t)NTOK_FULL*Hd]; // seqs + E_u[u] (exact)
__device__ float g_sequ_r[(size_t)NTOK_FULL*Hd]; // tf32-rounded copy
__device__ float g_ph  [(size_t)NT*Hd];          // relu(pairs @ W_hid^T), tf32-rounded
__device__ float g_dc  [(size_t)NT*128];         // relu(cat @ W_cd^T), tf32-rounded
__device__ float g_m   [(size_t)NT*Hd];          // relu(cat @ W_cdh^T), exact fp32

// Pre-rounded (tf32) weight / embedding copies
__device__ float g_Ed  [512*128];
__device__ float g_Ec  [512*128];
__device__ float g_Wcd [128*256];
__device__ float g_Whid[768*1536];
__device__ float g_Wcdh[768*896];

__device__ __forceinline__ float4 ld4(const float* p){
    return *reinterpret_cast<const float4*>(p);
}
__device__ __forceinline__ uint32_t f2tf32(float f){
    uint32_t o;
    asm("cvt.rna.tf32.f32 %0, %1;" : "=r"(o) : "f"(f));
    return o;
}
__device__ __forceinline__ void cpa16(uint32_t dst, const float* src){
    asm volatile("cp.async.cg.shared.global [%0], [%1], 16;\n" :: "r"(dst), "l"(src));
}

// ---------------------------------------------------------------------------
// Prep: dst = tf32_round(src), vectorized x4
// ---------------------------------------------------------------------------
__global__ void round_tf32_k(float* __restrict__ dst, const float* __restrict__ src, int n){
    int i = (blockIdx.x*blockDim.x + threadIdx.x)*4;
    if (i < n){
        float4 v = ld4(src + i);
        uint4 u = make_uint4(f2tf32(v.x), f2tf32(v.y), f2tf32(v.z), f2tf32(v.w));
        *reinterpret_cast<uint4*>(dst + i) = u;
    }
}

// ---------------------------------------------------------------------------
// Kernel: seqs_u = seqs + E_u[u]  (exact + rounded twin)
// ---------------------------------------------------------------------------
__global__ void add_ue_k(const float* __restrict__ seqs,
                         const int*   __restrict__ u,
                         const float* __restrict__ Eu){
    int t = blockIdx.x;
    int uid = __ldg(&u[t]);
    const float4* s4 = reinterpret_cast<const float4*>(seqs + (size_t)t*Hd);
    const float4* e4 = reinterpret_cast<const float4*>(Eu   + (size_t)uid*Hd);
    float4* d4 = reinterpret_cast<float4*>(g_sequ   + (size_t)t*Hd);
    uint4*  r4 = reinterpret_cast<uint4*> (g_sequ_r + (size_t)t*Hd);
    int i = threadIdx.x;
    float4 a = s4[i], b = e4[i];
    float4 o = make_float4(a.x+b.x, a.y+b.y, a.z+b.z, a.w+b.w);
    d4[i] = o;
    r4[i] = make_uint4(f2tf32(o.x), f2tf32(o.y), f2tf32(o.z), f2tf32(o.w));
}

// ---------------------------------------------------------------------------
// TF32 tensor-core GEMM, cp.async double-buffered pipeline.
//   C[t, n] = relu( sum_k A[t,k] * W[n,k] )
// Block 128x128, KTILE=32, 256 thr = 8 warps (4x2), warp 32x64, m16n8k8.
// All operands pre-rounded to tf32 bit patterns -> raw cp.async copies.
// MODE 0: A = [g_Ed[d[t]] | g_Ec[c[t]]],  K=256,  OUT=128, C=g_dc (rounded)
// MODE 1: A = g_sequ_r pairs,             K=1536, OUT=768, C=g_ph (rounded)
// MODE 2: A = [g_ph | g_dc],              K=896,  OUT=768, C=g_m  (exact)
// ---------------------------------------------------------------------------
#define KTILE 32
#define SSTR  36
#define TILE_U32 (128*SSTR)          // 4608 words
#define TILE_B   (TILE_U32*4)        // 18432 bytes
#define SMEM_TOT (4*TILE_B)          // 73728 bytes (2 bufs x (A,B))

template<int MODE, int K, int OUT, int ROUND>
__global__ __launch_bounds__(256, 2)
void gemm_tc_k(const int* __restrict__ I0, const int* __restrict__ I1,
               const float* __restrict__ W){
    extern __shared__ uint32_t smem[];
    const uint32_t sbase = (uint32_t)__cvta_generic_to_shared(smem);

    const int tid  = threadIdx.x;
    const int lane = tid & 31;
    const int warp = tid >> 5;
    const int m0   = blockIdx.y * 128;
    const int n0   = blockIdx.x * 128;
    const int wm   = (warp >> 1) * 32;
    const int wn   = (warp &  1) * 64;
    const int g    = lane >> 2;
    const int c    = lane &  3;

    float* Cout;
    if (MODE == 0)      Cout = g_dc;
    else if (MODE == 1) Cout = g_ph;
    else                Cout = g_m;

    // Per-thread load slots (4 chunks of 16B for A and for B each)
    int lr[4], lkq[4];
    const float* srcB[4];
    #pragma unroll
    for (int it = 0; it < 4; it++){
        int idx = tid + it*256;
        lr[it]  = idx >> 3;
        lkq[it] = (idx & 7) << 2;
        srcB[it] = W + (size_t)(n0 + lr[it])*K + lkq[it];
    }

    auto issue_tile = [&](int k0, int buf){
        uint32_t aB = sbase + buf*2*TILE_B;
        uint32_t bB = aB + TILE_B;
        #pragma unroll
        for (int it = 0; it < 4; it++){
            int r  = lr[it];
            int kq = lkq[it];
            int k  = k0 + kq;
            int t  = m0 + r; if (t >= NT) t = NT - 1;
            const float* sa;
            if (MODE == 0){
                sa = (k < 128) ? g_Ed + (size_t)__ldg(&I0[t])*128 + k
                               : g_Ec + (size_t)__ldg(&I1[t])*128 + (k-128);
            } else if (MODE == 1){
                int row = t + t/2047;  // b*2048 + s from t = b*2047 + s
                sa = g_sequ_r + (size_t)row*Hd + k;
            } else {
                sa = (k < 768) ? g_ph + (size_t)t*768 + k
                               : g_dc + (size_t)t*128 + (k-768);
            }
            cpa16(aB + (r*SSTR + kq)*4, sa);
            cpa16(bB + (r*SSTR + kq)*4, srcB[it] + k0);
        }
        asm volatile("cp.async.commit_group;\n" ::);
    };

    float acc[2][8][4];
    #pragma unroll
    for (int mi = 0; mi < 2; mi++)
        #pragma unroll
        for (int ni = 0; ni < 8; ni++)
            #pragma unroll
            for (int q = 0; q < 4; q++) acc[mi][ni][q] = 0.f;

    constexpr int NTILES = K / KTILE;
    issue_tile(0, 0);

    for (int ti = 0; ti < NTILES; ti++){
        asm volatile("cp.async.wait_group 0;\n" ::);
        __syncthreads();
        if (ti + 1 < NTILES) issue_tile((ti+1)*KTILE, (ti+1) & 1);

        const uint32_t* As = smem + (ti & 1)*2*TILE_U32;
        const uint32_t* Bs = As + TILE_U32;

        #pragma unroll
        for (int ks = 0; ks < KTILE; ks += 8){
            uint32_t afr[2][4], bfr[8][2];
            #pragma unroll
            for (int mi = 0; mi < 2; mi++){
                int r = wm + mi*16 + g;
                afr[mi][0] = As[ r     *SSTR + ks + c    ];
                afr[mi][1] = As[(r + 8)*SSTR + ks + c    ];
                afr[mi][2] = As[ r     *SSTR + ks + c + 4];
                afr[mi][3] = As[(r + 8)*SSTR + ks + c + 4];
            }
            #pragma unroll
            for (int ni = 0; ni < 8; ni++){
                int n = wn + ni*8 + g;
                bfr[ni][0] = Bs[n*SSTR + ks + c    ];
                bfr[ni][1] = Bs[n*SSTR + ks + c + 4];
            }
            #pragma unroll
            for (int mi = 0; mi < 2; mi++)
                #pragma unroll
                for (int ni = 0; ni < 8; ni++){
                    asm volatile(
                        "mma.sync.aligned.m16n8k8.row.col.f32.tf32.tf32.f32 "
                        "{%0,%1,%2,%3}, {%4,%5,%6,%7}, {%8,%9}, {%0,%1,%2,%3};\n"
                        : "+f"(acc[mi][ni][0]), "+f"(acc[mi][ni][1]),
                          "+f"(acc[mi][ni][2]), "+f"(acc[mi][ni][3])
                        : "r"(afr[mi][0]), "r"(afr[mi][1]),
                          "r"(afr[mi][2]), "r"(afr[mi][3]),
                          "r"(bfr[ni][0]), "r"(bfr[ni][1]));
                }
        }
        __syncthreads();
    }

    // Epilogue: ReLU (+ tf32 rounding when output feeds another GEMM)
    #pragma unroll
    for (int mi = 0; mi < 2; mi++){
        int rbase = m0 + wm + mi*16 + g;
        #pragma unroll
        for (int half = 0; half < 2; half++){
            int t = rbase + half*8;
            if (t < NT){
                #pragma unroll
                for (int ni = 0; ni < 8; ni++){
                    float x = fmaxf(acc[mi][ni][half*2 + 0], 0.f);
                    float y = fmaxf(acc[mi][ni][half*2 + 1], 0.f);
                    float2 v;
                    if (ROUND){
                        v.x = __uint_as_float(f2tf32(x));
                        v.y = __uint_as_float(f2tf32(y));
                    } else { v.x = x; v.y = y; }
                    *reinterpret_cast<float2*>(
                        Cout + (size_t)t*OUT + n0 + wn + ni*8 + 2*c) = v;
                }
            }
        }
    }
}

// ---------------------------------------------------------------------------
// Final: out[b,s] = seqs_u[b,s] + (s<S-1 ? m[b,s] : 0) + (s>=2 ? m[b,s-1] : 0)
// ---------------------------------------------------------------------------
__global__ void final_k(float* __restrict__ out){
    int t = blockIdx.x;
    int s = t & (Sl - 1);
    int b = t >> 11;
    int i = threadIdx.x;

    float4 v = reinterpret_cast<const float4*>(g_sequ + (size_t)t*Hd)[i];
    size_t mb = (size_t)b * (Sl - 1);
    if (s < Sl - 1){
        float4 mv = reinterpret_cast<const float4*>(g_m + (mb + s)*Hd)[i];
        v.x += mv.x; v.y += mv.y; v.z += mv.z; v.w += mv.w;
    }
    if (s >= 2){
        float4 mv = reinterpret_cast<const float4*>(g_m + (mb + s - 1)*Hd)[i];
        v.x += mv.x; v.y += mv.y; v.z += mv.z; v.w += mv.w;
    }
    reinterpret_cast<float4*>(out + (size_t)t*Hd)[i] = v;
}

// ---------------------------------------------------------------------------
extern "C" void kernel_launch(void* const* d_in, const int* in_sizes, int n_in,
                              void* d_out, int out_size){
    const float* seqs  = (const float*)d_in[0];
    const int*   d_idx = (const int*)  d_in[1];
    const int*   c_idx = (const int*)  d_in[2];
    const int*   u_idx = (const int*)  d_in[3];
    const float* E_d   = (const float*)d_in[4];
    const float* E_c   = (const float*)d_in[5];
    const float* E_u   = (const float*)d_in[6];
    const float* W_cd  = (const float*)d_in[7];
    const float* W_hid = (const float*)d_in[8];
    const float* W_cdh = (const float*)d_in[9];
    float* out = (float*)d_out;

    cudaFuncSetAttribute(gemm_tc_k<0,256,128,1>,  cudaFuncAttributeMaxDynamicSharedMemorySize, SMEM_TOT);
    cudaFuncSetAttribute(gemm_tc_k<1,1536,768,1>, cudaFuncAttributeMaxDynamicSharedMemorySize, SMEM_TOT);
    cudaFuncSetAttribute(gemm_tc_k<2,896,768,0>,  cudaFuncAttributeMaxDynamicSharedMemorySize, SMEM_TOT);

    float* pEd;   cudaGetSymbolAddress((void**)&pEd,   g_Ed);
    float* pEc;   cudaGetSymbolAddress((void**)&pEc,   g_Ec);
    float* pWcd;  cudaGetSymbolAddress((void**)&pWcd,  g_Wcd);
    float* pWhid; cudaGetSymbolAddress((void**)&pWhid, g_Whid);
    float* pWcdh; cudaGetSymbolAddress((void**)&pWcdh, g_Wcdh);

    // Pre-round weights/embeddings to tf32 bit patterns
    round_tf32_k<<<(512*128/4  +255)/256, 256>>>(pEd,   E_d,   512*128);
    round_tf32_k<<<(512*128/4  +255)/256, 256>>>(pEc,   E_c,   512*128);
    round_tf32_k<<<(128*256/4  +255)/256, 256>>>(pWcd,  W_cd,  128*256);
    round_tf32_k<<<(768*1536/4 +255)/256, 256>>>(pWhid, W_hid, 768*1536);
    round_tf32_k<<<(768*896/4  +255)/256, 256>>>(pWcdh, W_cdh, 768*896);

    // seqs_u = seqs + E_u[u] (exact + rounded)
    add_ue_k<<<NTOK_FULL, 192>>>(seqs, u_idx, E_u);

    const int MBLK = (NT + 127) / 128;   // 256

    // d_c = relu(cat(E_d[d], E_c[c]) @ W_cd^T)   [NT,128]
    gemm_tc_k<0, 256, 128, 1><<<dim3(1, MBLK), 256, SMEM_TOT>>>(d_idx, c_idx, pWcd);

    // ph = relu(pairs @ W_hid^T)                 [NT,768]
    gemm_tc_k<1, 1536, 768, 1><<<dim3(6, MBLK), 256, SMEM_TOT>>>(nullptr, nullptr, pWhid);

    // m = relu(cat(ph, d_c) @ W_cdh^T)           [NT,768]
    gemm_tc_k<2, 896, 768, 0><<<dim3(6, MBLK), 256, SMEM_TOT>>>(nullptr, nullptr, pWcdh);

    // out = seqs_u + shifted m adds
    final_k<<<NTOK_FULL, 192>>>(out);
}